// round 14
// baseline (speedup 1.0000x reference)
#include <cuda_runtime.h>
#include <cuda_bf16.h>

#define N_NODES 100000
#define N_EDGES 1600000
#define D_IN    128
#define D_HID   64
#define NB      ((N_NODES + 255) / 256)   // 391 scan blocks

// Scratch (allocation-free rule: __device__ globals)
__device__ int   g_cnt [N_NODES];
__device__ int   g_off [N_NODES];
__device__ int   g_cur [N_NODES];
__device__ int   g_bsum[512];
__device__ int   g_boff[512];
__device__ int   g_csr [N_EDGES];
__device__ float g_dis [N_NODES];
// h' rows channel-paired: slot p = channels (p, p+32) as float2 (256 B/row).
__device__ float2 g_h  [(size_t)N_NODES * 32];
__device__ float g_t   [N_NODES];

__device__ __forceinline__ int clampN(int v) {
    v = v < 0 ? 0 : v;
    return v >= N_NODES ? N_NODES - 1 : v;
}
__device__ __forceinline__ int edge_src(const int* ei, int e) { return clampN(ei[e]); }
__device__ __forceinline__ int edge_dst(const int* ei, int e) { return clampN(ei[N_EDGES + e]); }

// ---------------------------------------------------------------- counts
__global__ void k_cnt_init() {
    int i = blockIdx.x * 256 + threadIdx.x;
    if (i < N_NODES) g_cnt[i] = 0;
}
__global__ void k_deg(const int* __restrict__ ei) {
    int e = blockIdx.x * 256 + threadIdx.x;
    if (e < N_EDGES) atomicAdd(&g_cnt[edge_dst(ei, e)], 1);
}
__global__ void k_dis() {
    int i = blockIdx.x * 256 + threadIdx.x;
    if (i < N_NODES) g_dis[i] = rsqrtf((float)g_cnt[i] + 1.0f);   // +1 self-loop
}

// ---------------------------------------------------------------- h' = (x@W1)*dis  [PROFILED SLOT #4]
// L1-wavefront-minimized FFMA GEMM (tcgen05 unavailable: harness targets compute_103,
// not 103a). Per 4k-iter/warp: 8 LDS.128 x-broadcasts (1 phase each) + 4 LDS.64 w
// (2 phases) = 16 wf per 64 FFMA -> FFMA-bound (prior mixes were 24 wf per 32 FFMA).
// 128 thr = 4 warps x 8 rows = 32 rows/block; grid 3125 exact (no guards).
__global__ void __launch_bounds__(128) k_gemm(const float* __restrict__ x,
                                              const float* __restrict__ W1) {
    __shared__ float2 sW[D_IN * 32];   // sW[k*32+c] = {W1[k][c], W1[k][c+32]}  32 KB
    __shared__ float  sx[32 * D_IN];   // 32 rows x 128 k                       16 KB
    int tid = threadIdx.x;

    for (int idx = tid; idx < D_IN * 32; idx += 128) {
        int k = idx >> 5, c = idx & 31;
        sW[idx] = make_float2(W1[k * D_HID + c], W1[k * D_HID + c + 32]);
    }
    {   // stage x: 1024 float4, coalesced
        const float4* x4 = reinterpret_cast<const float4*>(x)
                         + (size_t)blockIdx.x * 32 * 32;
        float4* s4 = reinterpret_cast<float4*>(sx);
        for (int idx = tid; idx < 32 * 32; idx += 128) s4[idx] = __ldg(&x4[idx]);
    }
    __syncthreads();

    int warp = tid >> 5, lane = tid & 31;
    int rbase = warp * 8;                         // 8 rows per warp (local)

    float2 acc[8];
#pragma unroll
    for (int r = 0; r < 8; r++) acc[r] = make_float2(0.f, 0.f);

#pragma unroll 2
    for (int kb = 0; kb < D_IN / 4; kb++) {       // 4 k per iter
        float4 v[8];
#pragma unroll
        for (int r = 0; r < 8; r++)               // LDS.128 broadcast: 1 phase each
            v[r] = *reinterpret_cast<const float4*>(&sx[(rbase + r) * D_IN + kb * 4]);
#pragma unroll
        for (int kk = 0; kk < 4; kk++) {
            float2 w = sW[(kb * 4 + kk) * 32 + lane];   // LDS.64 conflict-free
#pragma unroll
            for (int r = 0; r < 8; r++) {
                float s = (&v[r].x)[kk];
                acc[r].x = fmaf(s, w.x, acc[r].x);
                acc[r].y = fmaf(s, w.y, acc[r].y);
            }
        }
    }

    int grow = blockIdx.x * 32 + rbase;
#pragma unroll
    for (int r = 0; r < 8; r++) {
        float dd = g_dis[grow + r];
        g_h[(size_t)(grow + r) * 32 + lane] =
            make_float2(acc[r].x * dd, acc[r].y * dd);
    }
}

// ---------------------------------------------------------------- 3-phase exclusive scan
__global__ void k_scan1() {
    __shared__ int s[256];
    int t = threadIdx.x, i = blockIdx.x * 256 + t;
    int c = (i < N_NODES) ? g_cnt[i] : 0;
    s[t] = c; __syncthreads();
#pragma unroll
    for (int d = 1; d < 256; d <<= 1) {
        int v = (t >= d) ? s[t - d] : 0;
        __syncthreads();
        s[t] += v;
        __syncthreads();
    }
    if (i < N_NODES) g_off[i] = s[t] - c;
    if (t == 255) g_bsum[blockIdx.x] = s[255];
}
__global__ void k_scan2() {
    __shared__ int s[512];
    int t = threadIdx.x;
    int c = (t < NB) ? g_bsum[t] : 0;
    s[t] = c; __syncthreads();
#pragma unroll
    for (int d = 1; d < 512; d <<= 1) {
        int v = (t >= d) ? s[t - d] : 0;
        __syncthreads();
        s[t] += v;
        __syncthreads();
    }
    if (t < NB) g_boff[t] = s[t] - c;
}
__global__ void k_scan3() {
    int i = blockIdx.x * 256 + threadIdx.x;
    if (i < N_NODES) {
        int o = g_off[i] + g_boff[blockIdx.x];
        g_off[i] = o;
        g_cur[i] = o;
    }
}

// ---------------------------------------------------------------- CSR fill (int atomics only)
__global__ void k_fill(const int* __restrict__ ei) {
    int e = blockIdx.x * 256 + threadIdx.x;
    if (e < N_EDGES) {
        int d = edge_dst(ei, e);
        int pos = atomicAdd(&g_cur[d], 1);
        g_csr[pos] = edge_src(ei, e);
    }
}

// ---------------------------------------------------------------- layer-1 gather + node op (fused)
// One warp per dst node; neighbor rows as one LDG.64/lane; csr indices via int4.
__global__ void k_gather1(const float* __restrict__ b1, const float* __restrict__ W2) {
    int n = (blockIdx.x * 256 + threadIdx.x) >> 5;
    int lane = threadIdx.x & 31;
    if (n >= N_NODES) return;

    float2 a = g_h[(size_t)n * 32 + lane];          // self-loop init
    float ax = a.x, ay = a.y;

    int j   = g_off[n];
    int end = j + g_cnt[n];
    while (j < end && (j & 3)) {
        float2 p = g_h[(size_t)g_csr[j] * 32 + lane];
        ax += p.x; ay += p.y;
        j++;
    }
    for (; j + 7 < end; j += 8) {
        int4 c0 = *reinterpret_cast<const int4*>(&g_csr[j]);
        int4 c1 = *reinterpret_cast<const int4*>(&g_csr[j + 4]);
        float2 p0 = g_h[(size_t)c0.x * 32 + lane], p1 = g_h[(size_t)c0.y * 32 + lane];
        float2 p2 = g_h[(size_t)c0.z * 32 + lane], p3 = g_h[(size_t)c0.w * 32 + lane];
        float2 p4 = g_h[(size_t)c1.x * 32 + lane], p5 = g_h[(size_t)c1.y * 32 + lane];
        float2 p6 = g_h[(size_t)c1.z * 32 + lane], p7 = g_h[(size_t)c1.w * 32 + lane];
        ax += ((p0.x + p1.x) + (p2.x + p3.x)) + ((p4.x + p5.x) + (p6.x + p7.x));
        ay += ((p0.y + p1.y) + (p2.y + p3.y)) + ((p4.y + p5.y) + (p6.y + p7.y));
    }
    for (; j + 3 < end; j += 4) {
        int4 c0 = *reinterpret_cast<const int4*>(&g_csr[j]);
        float2 p0 = g_h[(size_t)c0.x * 32 + lane], p1 = g_h[(size_t)c0.y * 32 + lane];
        float2 p2 = g_h[(size_t)c0.z * 32 + lane], p3 = g_h[(size_t)c0.w * 32 + lane];
        ax += (p0.x + p1.x) + (p2.x + p3.x);
        ay += (p0.y + p1.y) + (p2.y + p3.y);
    }
    for (; j < end; j++) {
        float2 p = g_h[(size_t)g_csr[j] * 32 + lane];
        ax += p.x; ay += p.y;
    }

    float d = g_dis[n];
    float z0 = fmaxf(fmaf(d, ax, b1[lane]),      0.f);
    float z1 = fmaxf(fmaf(d, ay, b1[lane + 32]), 0.f);
    float t = z0 * W2[lane] + z1 * W2[lane + 32];
#pragma unroll
    for (int off = 16; off; off >>= 1)
        t += __shfl_xor_sync(0xffffffffu, t, off);
    if (lane == 0) g_t[n] = t * d;
}

// ---------------------------------------------------------------- layer-2 gather + padded output
__global__ void k_l2(float* __restrict__ out, const float* __restrict__ b2) {
    int n = (blockIdx.x * 256 + threadIdx.x) >> 5;
    int lane = threadIdx.x & 31;
    if (n >= N_NODES) return;

    int beg = g_off[n];
    int end = beg + g_cnt[n];
    float sum = lane ? 0.f : g_t[n];                    // self-loop on lane 0
    for (int j = beg + lane; j < end; j += 32)
        sum += g_t[g_csr[j]];
#pragma unroll
    for (int off = 16; off; off >>= 1)
        sum += __shfl_xor_sync(0xffffffffu, sum, off);

    float y = g_dis[n] * sum + b2[0];
    float4 v = make_float4(0.f, 0.f, 0.f, 0.f);
    if (lane == 0) v.x = y;
    reinterpret_cast<float4*>(out)[(size_t)n * 32 + lane] = v;   // 128 floats/row
}

// ----------------------------------------------------------------
extern "C" void kernel_launch(void* const* d_in, const int* in_sizes, int n_in,
                              void* d_out, int out_size) {
    const float* x   = (const float*)d_in[0];
    const int*   ei  = (const int*)d_in[1];    // int32 [2, E]
    const float* W1  = (const float*)d_in[2];
    const float* b1  = (const float*)d_in[3];
    const float* W2  = (const float*)d_in[4];
    const float* b2  = (const float*)d_in[5];
    float*       out = (float*)d_out;

    k_cnt_init<<<NB, 256>>>();                              // 1
    k_deg     <<<(N_EDGES + 255) / 256, 256>>>(ei);         // 2
    k_dis     <<<NB, 256>>>();                              // 3
    k_gemm    <<<N_NODES / 32, 128>>>(x, W1);               // 4  <- profiled slot
    k_scan1   <<<NB, 256>>>();                              // 5
    k_scan2   <<<1, 512>>>();                               // 6
    k_scan3   <<<NB, 256>>>();                              // 7
    k_fill    <<<(N_EDGES + 255) / 256, 256>>>(ei);         // 8
    k_gather1 <<<(N_NODES * 32 + 255) / 256, 256>>>(b1, W2);// 9
    k_l2      <<<(N_NODES * 32 + 255) / 256, 256>>>(out, b2);// 10
}

// round 15
// speedup vs baseline: 1.3767x; 1.3767x over previous
#include <cuda_runtime.h>
#include <cuda_bf16.h>

#define N_NODES 100000
#define N_EDGES 1600000
#define D_IN    128
#define D_HID   64
#define NB      ((N_NODES + 255) / 256)   // 391 scan blocks

// Scratch (allocation-free rule: __device__ globals)
__device__ int   g_cnt [N_NODES];
__device__ int   g_off [N_NODES];
__device__ int   g_cur [N_NODES];
__device__ int   g_bsum[512];
__device__ int   g_boff[512];
__device__ int   g_csr [N_EDGES];
__device__ float g_dis [N_NODES];
// h' rows channel-paired: slot p = channels (p, p+32) as float2 (256 B/row).
__device__ float2 g_h  [(size_t)N_NODES * 32];
__device__ float g_t   [N_NODES];

__device__ __forceinline__ int clampN(int v) {
    v = v < 0 ? 0 : v;
    return v >= N_NODES ? N_NODES - 1 : v;
}
__device__ __forceinline__ int edge_src(const int* ei, int e) { return clampN(ei[e]); }
__device__ __forceinline__ int edge_dst(const int* ei, int e) { return clampN(ei[N_EDGES + e]); }

// ---------------------------------------------------------------- counts
__global__ void k_cnt_init() {
    int i = blockIdx.x * 256 + threadIdx.x;
    if (i < N_NODES) g_cnt[i] = 0;
}
__global__ void k_deg(const int* __restrict__ ei) {
    int e = blockIdx.x * 256 + threadIdx.x;
    if (e < N_EDGES) atomicAdd(&g_cnt[edge_dst(ei, e)], 1);
}
__global__ void k_dis() {
    int i = blockIdx.x * 256 + threadIdx.x;
    if (i < N_NODES) g_dis[i] = rsqrtf((float)g_cnt[i] + 1.0f);   // +1 self-loop
}

// ---------------------------------------------------------------- h' = (x@W1)*dis  [PROFILED SLOT #4]
// 2-D register-tiled FFMA GEMM. Thread tile 8 rows x 8 ch; warp = 4 row-groups x
// 8 ch-groups = 32 rows x 64 ch. Per k per warp: 8 scalar a-LDS (4 distinct addrs,
// scalar dedup -> 1 wf each; sx pitch 132 avoids row-stride bank collision) +
// 2 LDS.128 b-frag (4 wf each) = 16 wf per 64 FFMA. Prior rounds: ~1.5 FFMA/wf ->
// L1 wall at ~97us; this: 4 FFMA/wf -> FFMA-pipe-bound (~43k cyc/SM floor).
// 128 thr = 4 warps = 128 rows/block; smem = sW 32KB + sx 128x132x4B = 100,352 B.
#define SX_PITCH 132
#define GEMM_SMEM ((D_IN * D_HID + 128 * SX_PITCH) * 4)

__global__ void __launch_bounds__(128) k_gemm(const float* __restrict__ x,
                                              const float* __restrict__ W1) {
    extern __shared__ float sm[];
    float* sW = sm;                    // [128][64] row-major
    float* sx = sm + D_IN * D_HID;     // [128 rows][pitch 132]
    int tid = threadIdx.x;
    int base = blockIdx.x * 128;

    for (int idx = tid; idx < D_IN * D_HID; idx += 128) sW[idx] = W1[idx];
    {
        const float4* x4 = reinterpret_cast<const float4*>(x);
        for (int idx = tid; idx < 128 * 32; idx += 128) {
            int r = idx >> 5, q = idx & 31;                 // lanes -> consecutive q (coalesced)
            int gr = base + r; if (gr >= N_NODES) gr = N_NODES - 1;
            float4 v = __ldg(&x4[(size_t)gr * 32 + q]);
            *reinterpret_cast<float4*>(&sx[r * SX_PITCH + q * 4]) = v;  // 528B rows: 16B-aligned
        }
    }
    __syncthreads();

    int lane = tid & 31, warp = tid >> 5;
    int rg = lane >> 3, cg = lane & 7;                      // row-group 0..3, ch-group 0..7
    const float*  ap = sx + (warp * 32 + rg * 8) * SX_PITCH;
    const float4* bp = reinterpret_cast<const float4*>(sW) + cg * 2;

    float acc[8][8];
#pragma unroll
    for (int i = 0; i < 8; i++)
#pragma unroll
        for (int j = 0; j < 8; j++) acc[i][j] = 0.f;

#pragma unroll 4
    for (int k = 0; k < D_IN; k++) {
        float4 b0 = bp[k * 16];                             // W[k][c0..c0+3]
        float4 b1 = bp[k * 16 + 1];                         // W[k][c0+4..c0+7]
        float a[8];
#pragma unroll
        for (int i = 0; i < 8; i++) a[i] = ap[i * SX_PITCH + k];   // scalar: 4 addrs, dedup
#pragma unroll
        for (int i = 0; i < 8; i++) {
            acc[i][0] = fmaf(a[i], b0.x, acc[i][0]);
            acc[i][1] = fmaf(a[i], b0.y, acc[i][1]);
            acc[i][2] = fmaf(a[i], b0.z, acc[i][2]);
            acc[i][3] = fmaf(a[i], b0.w, acc[i][3]);
            acc[i][4] = fmaf(a[i], b1.x, acc[i][4]);
            acc[i][5] = fmaf(a[i], b1.y, acc[i][5]);
            acc[i][6] = fmaf(a[i], b1.z, acc[i][6]);
            acc[i][7] = fmaf(a[i], b1.w, acc[i][7]);
        }
    }

    // epilogue: channel-paired layout; cg<4 -> x-halves, cg>=4 -> y-halves
    float* gh = reinterpret_cast<float*>(g_h);
    int c0 = cg * 8;
#pragma unroll
    for (int i = 0; i < 8; i++) {
        int row = base + warp * 32 + rg * 8 + i;
        if (row < N_NODES) {
            float dd = g_dis[row];
#pragma unroll
            for (int j = 0; j < 8; j++) {
                int c = c0 + j;
                int slot = (c < 32) ? (c * 2) : ((c - 32) * 2 + 1);
                gh[(size_t)row * 64 + slot] = acc[i][j] * dd;
            }
        }
    }
}

// ---------------------------------------------------------------- 3-phase exclusive scan
__global__ void k_scan1() {
    __shared__ int s[256];
    int t = threadIdx.x, i = blockIdx.x * 256 + t;
    int c = (i < N_NODES) ? g_cnt[i] : 0;
    s[t] = c; __syncthreads();
#pragma unroll
    for (int d = 1; d < 256; d <<= 1) {
        int v = (t >= d) ? s[t - d] : 0;
        __syncthreads();
        s[t] += v;
        __syncthreads();
    }
    if (i < N_NODES) g_off[i] = s[t] - c;
    if (t == 255) g_bsum[blockIdx.x] = s[255];
}
__global__ void k_scan2() {
    __shared__ int s[512];
    int t = threadIdx.x;
    int c = (t < NB) ? g_bsum[t] : 0;
    s[t] = c; __syncthreads();
#pragma unroll
    for (int d = 1; d < 512; d <<= 1) {
        int v = (t >= d) ? s[t - d] : 0;
        __syncthreads();
        s[t] += v;
        __syncthreads();
    }
    if (t < NB) g_boff[t] = s[t] - c;
}
__global__ void k_scan3() {
    int i = blockIdx.x * 256 + threadIdx.x;
    if (i < N_NODES) {
        int o = g_off[i] + g_boff[blockIdx.x];
        g_off[i] = o;
        g_cur[i] = o;
    }
}

// ---------------------------------------------------------------- CSR fill (int atomics only)
__global__ void k_fill(const int* __restrict__ ei) {
    int e = blockIdx.x * 256 + threadIdx.x;
    if (e < N_EDGES) {
        int d = edge_dst(ei, e);
        int pos = atomicAdd(&g_cur[d], 1);
        g_csr[pos] = edge_src(ei, e);
    }
}

// ---------------------------------------------------------------- layer-1 gather + node op (fused)
// One warp per dst node; neighbor rows as one LDG.64/lane; csr indices via int4.
__global__ void k_gather1(const float* __restrict__ b1, const float* __restrict__ W2) {
    int n = (blockIdx.x * 256 + threadIdx.x) >> 5;
    int lane = threadIdx.x & 31;
    if (n >= N_NODES) return;

    float2 a = g_h[(size_t)n * 32 + lane];          // self-loop init
    float ax = a.x, ay = a.y;

    int j   = g_off[n];
    int end = j + g_cnt[n];
    while (j < end && (j & 3)) {
        float2 p = g_h[(size_t)g_csr[j] * 32 + lane];
        ax += p.x; ay += p.y;
        j++;
    }
    for (; j + 7 < end; j += 8) {
        int4 c0 = *reinterpret_cast<const int4*>(&g_csr[j]);
        int4 c1 = *reinterpret_cast<const int4*>(&g_csr[j + 4]);
        float2 p0 = g_h[(size_t)c0.x * 32 + lane], p1 = g_h[(size_t)c0.y * 32 + lane];
        float2 p2 = g_h[(size_t)c0.z * 32 + lane], p3 = g_h[(size_t)c0.w * 32 + lane];
        float2 p4 = g_h[(size_t)c1.x * 32 + lane], p5 = g_h[(size_t)c1.y * 32 + lane];
        float2 p6 = g_h[(size_t)c1.z * 32 + lane], p7 = g_h[(size_t)c1.w * 32 + lane];
        ax += ((p0.x + p1.x) + (p2.x + p3.x)) + ((p4.x + p5.x) + (p6.x + p7.x));
        ay += ((p0.y + p1.y) + (p2.y + p3.y)) + ((p4.y + p5.y) + (p6.y + p7.y));
    }
    for (; j + 3 < end; j += 4) {
        int4 c0 = *reinterpret_cast<const int4*>(&g_csr[j]);
        float2 p0 = g_h[(size_t)c0.x * 32 + lane], p1 = g_h[(size_t)c0.y * 32 + lane];
        float2 p2 = g_h[(size_t)c0.z * 32 + lane], p3 = g_h[(size_t)c0.w * 32 + lane];
        ax += (p0.x + p1.x) + (p2.x + p3.x);
        ay += (p0.y + p1.y) + (p2.y + p3.y);
    }
    for (; j < end; j++) {
        float2 p = g_h[(size_t)g_csr[j] * 32 + lane];
        ax += p.x; ay += p.y;
    }

    float d = g_dis[n];
    float z0 = fmaxf(fmaf(d, ax, b1[lane]),      0.f);
    float z1 = fmaxf(fmaf(d, ay, b1[lane + 32]), 0.f);
    float t = z0 * W2[lane] + z1 * W2[lane + 32];
#pragma unroll
    for (int off = 16; off; off >>= 1)
        t += __shfl_xor_sync(0xffffffffu, t, off);
    if (lane == 0) g_t[n] = t * d;
}

// ---------------------------------------------------------------- layer-2 gather + padded output
__global__ void k_l2(float* __restrict__ out, const float* __restrict__ b2) {
    int n = (blockIdx.x * 256 + threadIdx.x) >> 5;
    int lane = threadIdx.x & 31;
    if (n >= N_NODES) return;

    int beg = g_off[n];
    int end = beg + g_cnt[n];
    float sum = lane ? 0.f : g_t[n];                    // self-loop on lane 0
    for (int j = beg + lane; j < end; j += 32)
        sum += g_t[g_csr[j]];
#pragma unroll
    for (int off = 16; off; off >>= 1)
        sum += __shfl_xor_sync(0xffffffffu, sum, off);

    float y = g_dis[n] * sum + b2[0];
    float4 v = make_float4(0.f, 0.f, 0.f, 0.f);
    if (lane == 0) v.x = y;
    reinterpret_cast<float4*>(out)[(size_t)n * 32 + lane] = v;   // 128 floats/row
}

// ----------------------------------------------------------------
extern "C" void kernel_launch(void* const* d_in, const int* in_sizes, int n_in,
                              void* d_out, int out_size) {
    const float* x   = (const float*)d_in[0];
    const int*   ei  = (const int*)d_in[1];    // int32 [2, E]
    const float* W1  = (const float*)d_in[2];
    const float* b1  = (const float*)d_in[3];
    const float* W2  = (const float*)d_in[4];
    const float* b2  = (const float*)d_in[5];
    float*       out = (float*)d_out;

    cudaFuncSetAttribute(k_gemm, cudaFuncAttributeMaxDynamicSharedMemorySize, GEMM_SMEM);

    k_cnt_init<<<NB, 256>>>();                              // 1
    k_deg     <<<(N_EDGES + 255) / 256, 256>>>(ei);         // 2
    k_dis     <<<NB, 256>>>();                              // 3
    k_gemm    <<<(N_NODES + 127) / 128, 128, GEMM_SMEM>>>(x, W1); // 4 <- profiled slot
    k_scan1   <<<NB, 256>>>();                              // 5
    k_scan2   <<<1, 512>>>();                               // 6
    k_scan3   <<<NB, 256>>>();                              // 7
    k_fill    <<<(N_EDGES + 255) / 256, 256>>>(ei);         // 8
    k_gather1 <<<(N_NODES * 32 + 255) / 256, 256>>>(b1, W2);// 9
    k_l2      <<<(N_NODES * 32 + 255) / 256, 256>>>(out, b2);// 10
}

// round 16
// speedup vs baseline: 1.4904x; 1.0826x over previous
#include <cuda_runtime.h>
#include <cuda_bf16.h>

#define N_NODES 100000
#define N_EDGES 1600000
#define D_IN    128
#define D_HID   64
#define NB      ((N_NODES + 255) / 256)   // 391 scan blocks

// Scratch (allocation-free rule: __device__ globals)
__device__ int   g_cnt [N_NODES];
__device__ int   g_off [N_NODES];
__device__ int   g_cur [N_NODES];
__device__ int   g_bsum[512];
__device__ int   g_boff[512];
__device__ int   g_csr [N_EDGES];
__device__ float g_dis [N_NODES];
// h' rows channel-paired ADJACENT: slot p = channels (2p, 2p+1) as float2 (256 B/row).
__device__ float2 g_h  [(size_t)N_NODES * 32];
__device__ float g_t   [N_NODES];

__device__ __forceinline__ int clampN(int v) {
    v = v < 0 ? 0 : v;
    return v >= N_NODES ? N_NODES - 1 : v;
}
__device__ __forceinline__ int edge_src(const int* ei, int e) { return clampN(ei[e]); }
__device__ __forceinline__ int edge_dst(const int* ei, int e) { return clampN(ei[N_EDGES + e]); }

// ---- packed f32x2 helpers (elementwise dual fp32 FMA; ran correctly in R8) ----
__device__ __forceinline__ void fma2(unsigned long long& a, unsigned long long b,
                                     unsigned long long c) {
    asm("fma.rn.f32x2 %0, %1, %2, %0;" : "+l"(a) : "l"(b), "l"(c));
}
__device__ __forceinline__ unsigned long long bcast2(float s) {
    unsigned long long r;
    asm("mov.b64 %0, {%1, %1};" : "=l"(r) : "f"(s));
    return r;
}
__device__ __forceinline__ float2 unpack2(unsigned long long a) {
    float2 r;
    asm("mov.b64 {%0, %1}, %2;" : "=f"(r.x), "=f"(r.y) : "l"(a));
    return r;
}

// ---------------------------------------------------------------- counts
__global__ void k_cnt_init() {
    int i = blockIdx.x * 256 + threadIdx.x;
    if (i < N_NODES) g_cnt[i] = 0;
}
__global__ void k_deg(const int* __restrict__ ei) {
    int e = blockIdx.x * 256 + threadIdx.x;
    if (e < N_EDGES) atomicAdd(&g_cnt[edge_dst(ei, e)], 1);
}
__global__ void k_dis() {
    int i = blockIdx.x * 256 + threadIdx.x;
    if (i < N_NODES) g_dis[i] = rsqrtf((float)g_cnt[i] + 1.0f);   // +1 self-loop
}

// ---------------------------------------------------------------- h' = (x@W1)*dis  [PROFILED SLOT #4]
// FFMA2 2-D register-tiled GEMM. 256 thr = 8 warps; block = 256 rows; warp = 32
// rows x 64 ch; thread = 8 rows x 8 ch, acc = 32 packed f32x2 (adjacent ch pairs).
// Per k/thread: 8 scalar a-LDS (4 rg addrs on banks 0/4/8/12 via pitch 132 +
// row-stride-4 mapping -> 1 wf each) + 2 LDS.128 b (pre-paired longlong2) +
// 8 bcast movs (alu, overlapped) + 32 FFMA2. Per-SM/k: 256 FFMA2 / 2 = 128 cyc
// >= 96 L1-wf -> fma-pipe-bound; floor ~24us. R15's miss: 4 warps/SM (occ 12%)
// was latency-starved; 8 warps fixes it. FFMA2 pays here: 1 mov per 4 FFMA2
// (R8's failure was 1:1).
#define SX_PITCH 132
#define GEMM_SMEM ((D_IN * D_HID + 256 * SX_PITCH) * 4)   // 32KB + 135KB = 167,936? -> compute

__global__ void __launch_bounds__(256) k_gemm(const float* __restrict__ x,
                                              const float* __restrict__ W1) {
    extern __shared__ float sm[];
    float* sW = sm;                    // [128][64] row-major (16B aligned)
    float* sx = sm + D_IN * D_HID;     // [256 rows][pitch 132] (528B rows, 16B aligned)
    int tid = threadIdx.x;
    int base = blockIdx.x * 256;

    for (int idx = tid; idx < D_IN * D_HID; idx += 256) sW[idx] = W1[idx];
    {
        const float4* x4 = reinterpret_cast<const float4*>(x);
        for (int idx = tid; idx < 256 * 32; idx += 256) {
            int r = idx >> 5, q = idx & 31;               // lanes -> consecutive q (coalesced LDG)
            int gr = base + r; if (gr >= N_NODES) gr = N_NODES - 1;
            float4 v = __ldg(&x4[(size_t)gr * 32 + q]);
            *reinterpret_cast<float4*>(&sx[r * SX_PITCH + q * 4]) = v;   // sequential STS.128
        }
    }
    __syncthreads();

    int lane = tid & 31, warp = tid >> 5;
    int rg = lane >> 3, cg = lane & 7;                    // rows: warp*32 + rg + 4i; ch: cg*8..+7
    const float* ap = sx + (warp * 32 + rg) * SX_PITCH;
    const longlong2* bp = reinterpret_cast<const longlong2*>(sW);   // 16B units

    unsigned long long acc[8][4];
#pragma unroll
    for (int i = 0; i < 8; i++)
#pragma unroll
        for (int j = 0; j < 4; j++) acc[i][j] = 0ull;     // {0.f,0.f}

#pragma unroll 4
    for (int k = 0; k < D_IN; k++) {
        longlong2 bv0 = bp[k * 16 + cg * 2];              // {W[k][c0..c0+3]} as 2 f32x2
        longlong2 bv1 = bp[k * 16 + cg * 2 + 1];          // {W[k][c0+4..c0+7]}
        float a[8];
#pragma unroll
        for (int i = 0; i < 8; i++) a[i] = ap[i * 4 * SX_PITCH + k];  // 4 rg addrs, dedup, 1 wf
#pragma unroll
        for (int i = 0; i < 8; i++) {
            unsigned long long a2 = bcast2(a[i]);         // 1 mov per 4 FFMA2
            fma2(acc[i][0], a2, (unsigned long long)bv0.x);
            fma2(acc[i][1], a2, (unsigned long long)bv0.y);
            fma2(acc[i][2], a2, (unsigned long long)bv1.x);
            fma2(acc[i][3], a2, (unsigned long long)bv1.y);
        }
    }

    // epilogue: thread owns ch pairs (c0+2j, c0+2j+1) = g_h slots cg*4+j -> 2 float4 stores
#pragma unroll
    for (int i = 0; i < 8; i++) {
        int row = base + warp * 32 + rg + i * 4;
        if (row < N_NODES) {
            float dd = g_dis[row];
            float2 u0 = unpack2(acc[i][0]), u1 = unpack2(acc[i][1]);
            float2 u2 = unpack2(acc[i][2]), u3 = unpack2(acc[i][3]);
            float4* gh = reinterpret_cast<float4*>(&g_h[(size_t)row * 32 + cg * 4]);
            gh[0] = make_float4(u0.x * dd, u0.y * dd, u1.x * dd, u1.y * dd);
            gh[1] = make_float4(u2.x * dd, u2.y * dd, u3.x * dd, u3.y * dd);
        }
    }
}

// ---------------------------------------------------------------- 3-phase exclusive scan
__global__ void k_scan1() {
    __shared__ int s[256];
    int t = threadIdx.x, i = blockIdx.x * 256 + t;
    int c = (i < N_NODES) ? g_cnt[i] : 0;
    s[t] = c; __syncthreads();
#pragma unroll
    for (int d = 1; d < 256; d <<= 1) {
        int v = (t >= d) ? s[t - d] : 0;
        __syncthreads();
        s[t] += v;
        __syncthreads();
    }
    if (i < N_NODES) g_off[i] = s[t] - c;
    if (t == 255) g_bsum[blockIdx.x] = s[255];
}
__global__ void k_scan2() {
    __shared__ int s[512];
    int t = threadIdx.x;
    int c = (t < NB) ? g_bsum[t] : 0;
    s[t] = c; __syncthreads();
#pragma unroll
    for (int d = 1; d < 512; d <<= 1) {
        int v = (t >= d) ? s[t - d] : 0;
        __syncthreads();
        s[t] += v;
        __syncthreads();
    }
    if (t < NB) g_boff[t] = s[t] - c;
}
__global__ void k_scan3() {
    int i = blockIdx.x * 256 + threadIdx.x;
    if (i < N_NODES) {
        int o = g_off[i] + g_boff[blockIdx.x];
        g_off[i] = o;
        g_cur[i] = o;
    }
}

// ---------------------------------------------------------------- CSR fill (int atomics only)
__global__ void k_fill(const int* __restrict__ ei) {
    int e = blockIdx.x * 256 + threadIdx.x;
    if (e < N_EDGES) {
        int d = edge_dst(ei, e);
        int pos = atomicAdd(&g_cur[d], 1);
        g_csr[pos] = edge_src(ei, e);
    }
}

// ---------------------------------------------------------------- layer-1 gather + node op (fused)
// One warp per dst node; neighbor rows as one LDG.64/lane; csr indices via int4.
// g_h slot `lane` holds channels (2*lane, 2*lane+1) -> b1/W2 indexed to match.
__global__ void k_gather1(const float* __restrict__ b1, const float* __restrict__ W2) {
    int n = (blockIdx.x * 256 + threadIdx.x) >> 5;
    int lane = threadIdx.x & 31;
    if (n >= N_NODES) return;

    float2 a = g_h[(size_t)n * 32 + lane];          // self-loop init
    float ax = a.x, ay = a.y;

    int j   = g_off[n];
    int end = j + g_cnt[n];
    while (j < end && (j & 3)) {
        float2 p = g_h[(size_t)g_csr[j] * 32 + lane];
        ax += p.x; ay += p.y;
        j++;
    }
    for (; j + 7 < end; j += 8) {
        int4 c0 = *reinterpret_cast<const int4*>(&g_csr[j]);
        int4 c1 = *reinterpret_cast<const int4*>(&g_csr[j + 4]);
        float2 p0 = g_h[(size_t)c0.x * 32 + lane], p1 = g_h[(size_t)c0.y * 32 + lane];
        float2 p2 = g_h[(size_t)c0.z * 32 + lane], p3 = g_h[(size_t)c0.w * 32 + lane];
        float2 p4 = g_h[(size_t)c1.x * 32 + lane], p5 = g_h[(size_t)c1.y * 32 + lane];
        float2 p6 = g_h[(size_t)c1.z * 32 + lane], p7 = g_h[(size_t)c1.w * 32 + lane];
        ax += ((p0.x + p1.x) + (p2.x + p3.x)) + ((p4.x + p5.x) + (p6.x + p7.x));
        ay += ((p0.y + p1.y) + (p2.y + p3.y)) + ((p4.y + p5.y) + (p6.y + p7.y));
    }
    for (; j + 3 < end; j += 4) {
        int4 c0 = *reinterpret_cast<const int4*>(&g_csr[j]);
        float2 p0 = g_h[(size_t)c0.x * 32 + lane], p1 = g_h[(size_t)c0.y * 32 + lane];
        float2 p2 = g_h[(size_t)c0.z * 32 + lane], p3 = g_h[(size_t)c0.w * 32 + lane];
        ax += (p0.x + p1.x) + (p2.x + p3.x);
        ay += (p0.y + p1.y) + (p2.y + p3.y);
    }
    for (; j < end; j++) {
        float2 p = g_h[(size_t)g_csr[j] * 32 + lane];
        ax += p.x; ay += p.y;
    }

    float d = g_dis[n];
    float z0 = fmaxf(fmaf(d, ax, b1[2 * lane]),     0.f);   // channel 2*lane
    float z1 = fmaxf(fmaf(d, ay, b1[2 * lane + 1]), 0.f);   // channel 2*lane+1
    float t = z0 * W2[2 * lane] + z1 * W2[2 * lane + 1];
#pragma unroll
    for (int off = 16; off; off >>= 1)
        t += __shfl_xor_sync(0xffffffffu, t, off);
    if (lane == 0) g_t[n] = t * d;
}

// ---------------------------------------------------------------- layer-2 gather + padded output
__global__ void k_l2(float* __restrict__ out, const float* __restrict__ b2) {
    int n = (blockIdx.x * 256 + threadIdx.x) >> 5;
    int lane = threadIdx.x & 31;
    if (n >= N_NODES) return;

    int beg = g_off[n];
    int end = beg + g_cnt[n];
    float sum = lane ? 0.f : g_t[n];                    // self-loop on lane 0
    for (int j = beg + lane; j < end; j += 32)
        sum += g_t[g_csr[j]];
#pragma unroll
    for (int off = 16; off; off >>= 1)
        sum += __shfl_xor_sync(0xffffffffu, sum, off);

    float y = g_dis[n] * sum + b2[0];
    float4 v = make_float4(0.f, 0.f, 0.f, 0.f);
    if (lane == 0) v.x = y;
    reinterpret_cast<float4*>(out)[(size_t)n * 32 + lane] = v;   // 128 floats/row
}

// ----------------------------------------------------------------
extern "C" void kernel_launch(void* const* d_in, const int* in_sizes, int n_in,
                              void* d_out, int out_size) {
    const float* x   = (const float*)d_in[0];
    const int*   ei  = (const int*)d_in[1];    // int32 [2, E]
    const float* W1  = (const float*)d_in[2];
    const float* b1  = (const float*)d_in[3];
    const float* W2  = (const float*)d_in[4];
    const float* b2  = (const float*)d_in[5];
    float*       out = (float*)d_out;

    cudaFuncSetAttribute(k_gemm, cudaFuncAttributeMaxDynamicSharedMemorySize, GEMM_SMEM);

    k_cnt_init<<<NB, 256>>>();                              // 1
    k_deg     <<<(N_EDGES + 255) / 256, 256>>>(ei);         // 2
    k_dis     <<<NB, 256>>>();                              // 3
    k_gemm    <<<(N_NODES + 255) / 256, 256, GEMM_SMEM>>>(x, W1); // 4 <- profiled slot
    k_scan1   <<<NB, 256>>>();                              // 5
    k_scan2   <<<1, 512>>>();                               // 6
    k_scan3   <<<NB, 256>>>();                              // 7
    k_fill    <<<(N_EDGES + 255) / 256, 256>>>(ei);         // 8
    k_gather1 <<<(N_NODES * 32 + 255) / 256, 256>>>(b1, W2);// 9
    k_l2      <<<(N_NODES * 32 + 255) / 256, 256>>>(out, b2);// 10
}

// round 17
// speedup vs baseline: 1.6676x; 1.1189x over previous
#include <cuda_runtime.h>
#include <cuda_bf16.h>

#define N_NODES 100000
#define N_EDGES 1600000
#define D_IN    128
#define D_HID   64
#define NB      ((N_NODES + 255) / 256)   // 391 scan blocks

// Scratch (allocation-free rule: __device__ globals)
__device__ int   g_cnt [N_NODES];
__device__ int   g_off [N_NODES];
__device__ int   g_cur [N_NODES];
__device__ int   g_bsum[512];
__device__ int   g_boff[512];
__device__ int   g_csr [N_EDGES];
__device__ float g_dis [N_NODES];
// h rows UNSCALED (dis applied in gather1), channel-paired ADJACENT:
// slot p = channels (2p, 2p+1) as float2 (256 B/row).
__device__ float2 g_h  [(size_t)N_NODES * 32];
__device__ float g_t   [N_NODES];

__device__ __forceinline__ int clampN(int v) {
    v = v < 0 ? 0 : v;
    return v >= N_NODES ? N_NODES - 1 : v;
}
__device__ __forceinline__ int edge_src(const int* ei, int e) { return clampN(ei[e]); }
__device__ __forceinline__ int edge_dst(const int* ei, int e) { return clampN(ei[N_EDGES + e]); }

// ---- packed f32x2 helpers ----
__device__ __forceinline__ void fma2(unsigned long long& a, unsigned long long b,
                                     unsigned long long c) {
    asm("fma.rn.f32x2 %0, %1, %2, %0;" : "+l"(a) : "l"(b), "l"(c));
}
__device__ __forceinline__ unsigned long long bcast2(float s) {
    unsigned long long r;
    asm("mov.b64 %0, {%1, %1};" : "=l"(r) : "f"(s));
    return r;
}
__device__ __forceinline__ float2 unpack2(unsigned long long a) {
    float2 r;
    asm("mov.b64 {%0, %1}, %2;" : "=f"(r.x), "=f"(r.y) : "l"(a));
    return r;
}

// ---------------------------------------------------------------- counts
__global__ void k_cnt_init() {
    int i = blockIdx.x * 256 + threadIdx.x;
    if (i < N_NODES) g_cnt[i] = 0;
}
__global__ void k_deg(const int* __restrict__ ei) {
    int e = blockIdx.x * 256 + threadIdx.x;
    if (e < N_EDGES) atomicAdd(&g_cnt[edge_dst(ei, e)], 1);
}
__global__ void k_dis() {
    int i = blockIdx.x * 256 + threadIdx.x;
    if (i < N_NODES) g_dis[i] = rsqrtf((float)g_cnt[i] + 1.0f);   // +1 self-loop
}

// ---------------------------------------------------------------- h = x@W1 (UNSCALED)
// No sx stage: a-frags via LDG.64 from gmem (4 distinct rows/warp -> 4 sectors,
// re-hit across 8 consecutive k; L2 traffic = x once). smem = sW 32KB only ->
// __launch_bounds__(256,2) = 16 warps/SM (R16 was 8, latency-starved at issue 27.5%).
// Tile: warp 32 rows x 64 ch, thread 8 rows x 8 ch, acc = 32 packed f32x2.
__global__ void __launch_bounds__(256, 2) k_gemm(const float* __restrict__ x,
                                                 const float* __restrict__ W1) {
    __shared__ float sW[D_IN * D_HID];   // natural row-major = adjacent-pair ready (32 KB)
    int tid = threadIdx.x;
    int base = blockIdx.x * 256;
    for (int idx = tid; idx < D_IN * D_HID; idx += 256) sW[idx] = W1[idx];
    __syncthreads();

    int lane = tid & 31, warp = tid >> 5;
    int rg = lane >> 3, cg = lane & 7;             // rows: base+warp*32+rg+4i; ch: cg*8..+7
    const longlong2* bp = reinterpret_cast<const longlong2*>(sW);  // 16B units

    unsigned long long acc[8][4];
#pragma unroll
    for (int i = 0; i < 8; i++)
#pragma unroll
        for (int j = 0; j < 4; j++) acc[i][j] = 0ull;

    int row0 = base + warp * 32 + rg;
    bool full = (base + 256 <= N_NODES);           // 390 of 391 blocks
    const float* ap = x + (size_t)(full ? row0 : clampN(row0)) * D_IN;

    if (full) {
#pragma unroll 2
        for (int kb = 0; kb < D_IN / 2; kb++) {    // 2 k per iter
            float2 av[8];
#pragma unroll
            for (int i = 0; i < 8; i++)            // LDG.64, imm offsets, sector-hit
                av[i] = __ldg(reinterpret_cast<const float2*>(ap + i * 4 * D_IN) + kb);
            longlong2 b00 = bp[(2 * kb) * 16 + cg * 2];
            longlong2 b01 = bp[(2 * kb) * 16 + cg * 2 + 1];
            longlong2 b10 = bp[(2 * kb + 1) * 16 + cg * 2];
            longlong2 b11 = bp[(2 * kb + 1) * 16 + cg * 2 + 1];
#pragma unroll
            for (int i = 0; i < 8; i++) {
                unsigned long long a0 = bcast2(av[i].x);
                fma2(acc[i][0], a0, (unsigned long long)b00.x);
                fma2(acc[i][1], a0, (unsigned long long)b00.y);
                fma2(acc[i][2], a0, (unsigned long long)b01.x);
                fma2(acc[i][3], a0, (unsigned long long)b01.y);
                unsigned long long a1 = bcast2(av[i].y);
                fma2(acc[i][0], a1, (unsigned long long)b10.x);
                fma2(acc[i][1], a1, (unsigned long long)b10.y);
                fma2(acc[i][2], a1, (unsigned long long)b11.x);
                fma2(acc[i][3], a1, (unsigned long long)b11.y);
            }
        }
    } else {                                       // tail block: clamped row pointers
        const float* apc[8];
#pragma unroll
        for (int i = 0; i < 8; i++) apc[i] = x + (size_t)clampN(row0 + i * 4) * D_IN;
        for (int kb = 0; kb < D_IN / 2; kb++) {
            float2 av[8];
#pragma unroll
            for (int i = 0; i < 8; i++)
                av[i] = __ldg(reinterpret_cast<const float2*>(apc[i]) + kb);
            longlong2 b00 = bp[(2 * kb) * 16 + cg * 2];
            longlong2 b01 = bp[(2 * kb) * 16 + cg * 2 + 1];
            longlong2 b10 = bp[(2 * kb + 1) * 16 + cg * 2];
            longlong2 b11 = bp[(2 * kb + 1) * 16 + cg * 2 + 1];
#pragma unroll
            for (int i = 0; i < 8; i++) {
                unsigned long long a0 = bcast2(av[i].x);
                fma2(acc[i][0], a0, (unsigned long long)b00.x);
                fma2(acc[i][1], a0, (unsigned long long)b00.y);
                fma2(acc[i][2], a0, (unsigned long long)b01.x);
                fma2(acc[i][3], a0, (unsigned long long)b01.y);
                unsigned long long a1 = bcast2(av[i].y);
                fma2(acc[i][0], a1, (unsigned long long)b10.x);
                fma2(acc[i][1], a1, (unsigned long long)b10.y);
                fma2(acc[i][2], a1, (unsigned long long)b11.x);
                fma2(acc[i][3], a1, (unsigned long long)b11.y);
            }
        }
    }

    // epilogue: thread owns g_h slots cg*4..cg*4+3 -> 2 float4 stores (UNSCALED)
#pragma unroll
    for (int i = 0; i < 8; i++) {
        int row = base + warp * 32 + rg + i * 4;
        if (row < N_NODES) {
            float2 u0 = unpack2(acc[i][0]), u1 = unpack2(acc[i][1]);
            float2 u2 = unpack2(acc[i][2]), u3 = unpack2(acc[i][3]);
            float4* gh = reinterpret_cast<float4*>(&g_h[(size_t)row * 32 + cg * 4]);
            gh[0] = make_float4(u0.x, u0.y, u1.x, u1.y);
            gh[1] = make_float4(u2.x, u2.y, u3.x, u3.y);
        }
    }
}

// ---------------------------------------------------------------- 3-phase exclusive scan
__global__ void k_scan1() {
    __shared__ int s[256];
    int t = threadIdx.x, i = blockIdx.x * 256 + t;
    int c = (i < N_NODES) ? g_cnt[i] : 0;
    s[t] = c; __syncthreads();
#pragma unroll
    for (int d = 1; d < 256; d <<= 1) {
        int v = (t >= d) ? s[t - d] : 0;
        __syncthreads();
        s[t] += v;
        __syncthreads();
    }
    if (i < N_NODES) g_off[i] = s[t] - c;
    if (t == 255) g_bsum[blockIdx.x] = s[255];
}
__global__ void k_scan2() {
    __shared__ int s[512];
    int t = threadIdx.x;
    int c = (t < NB) ? g_bsum[t] : 0;
    s[t] = c; __syncthreads();
#pragma unroll
    for (int d = 1; d < 512; d <<= 1) {
        int v = (t >= d) ? s[t - d] : 0;
        __syncthreads();
        s[t] += v;
        __syncthreads();
    }
    if (t < NB) g_boff[t] = s[t] - c;
}
__global__ void k_scan3() {
    int i = blockIdx.x * 256 + threadIdx.x;
    if (i < N_NODES) {
        int o = g_off[i] + g_boff[blockIdx.x];
        g_off[i] = o;
        g_cur[i] = o;
    }
}

// ---------------------------------------------------------------- CSR fill (int atomics only)
__global__ void k_fill(const int* __restrict__ ei) {
    int e = blockIdx.x * 256 + threadIdx.x;
    if (e < N_EDGES) {
        int d = edge_dst(ei, e);
        int pos = atomicAdd(&g_cur[d], 1);
        g_csr[pos] = edge_src(ei, e);
    }
}

// ---------------------------------------------------------------- layer-1 gather + node op (fused)
// One warp per dst node. h is UNSCALED: accumulate h[s]*dis[s] (per-edge uniform
// dis load, FADD->FFMA same count); self term h[n]*dis[n].
__global__ void k_gather1(const float* __restrict__ b1, const float* __restrict__ W2) {
    int n = (blockIdx.x * 256 + threadIdx.x) >> 5;
    int lane = threadIdx.x & 31;
    if (n >= N_NODES) return;

    float d = g_dis[n];
    float2 a = g_h[(size_t)n * 32 + lane];
    float ax = a.x * d, ay = a.y * d;               // self-loop

    int j   = g_off[n];
    int end = j + g_cnt[n];
    while (j < end && (j & 3)) {
        int s = g_csr[j];
        float ds = g_dis[s];
        float2 p = g_h[(size_t)s * 32 + lane];
        ax = fmaf(p.x, ds, ax); ay = fmaf(p.y, ds, ay);
        j++;
    }
    for (; j + 7 < end; j += 8) {
        int4 c0 = *reinterpret_cast<const int4*>(&g_csr[j]);
        int4 c1 = *reinterpret_cast<const int4*>(&g_csr[j + 4]);
        float ds0 = g_dis[c0.x], ds1 = g_dis[c0.y], ds2 = g_dis[c0.z], ds3 = g_dis[c0.w];
        float ds4 = g_dis[c1.x], ds5 = g_dis[c1.y], ds6 = g_dis[c1.z], ds7 = g_dis[c1.w];
        float2 p0 = g_h[(size_t)c0.x * 32 + lane], p1 = g_h[(size_t)c0.y * 32 + lane];
        float2 p2 = g_h[(size_t)c0.z * 32 + lane], p3 = g_h[(size_t)c0.w * 32 + lane];
        float2 p4 = g_h[(size_t)c1.x * 32 + lane], p5 = g_h[(size_t)c1.y * 32 + lane];
        float2 p6 = g_h[(size_t)c1.z * 32 + lane], p7 = g_h[(size_t)c1.w * 32 + lane];
        ax = fmaf(p0.x, ds0, ax); ay = fmaf(p0.y, ds0, ay);
        ax = fmaf(p1.x, ds1, ax); ay = fmaf(p1.y, ds1, ay);
        ax = fmaf(p2.x, ds2, ax); ay = fmaf(p2.y, ds2, ay);
        ax = fmaf(p3.x, ds3, ax); ay = fmaf(p3.y, ds3, ay);
        ax = fmaf(p4.x, ds4, ax); ay = fmaf(p4.y, ds4, ay);
        ax = fmaf(p5.x, ds5, ax); ay = fmaf(p5.y, ds5, ay);
        ax = fmaf(p6.x, ds6, ax); ay = fmaf(p6.y, ds6, ay);
        ax = fmaf(p7.x, ds7, ax); ay = fmaf(p7.y, ds7, ay);
    }
    for (; j < end; j++) {
        int s = g_csr[j];
        float ds = g_dis[s];
        float2 p = g_h[(size_t)s * 32 + lane];
        ax = fmaf(p.x, ds, ax); ay = fmaf(p.y, ds, ay);
    }

    float z0 = fmaxf(fmaf(d, ax, b1[2 * lane]),     0.f);   // channel 2*lane
    float z1 = fmaxf(fmaf(d, ay, b1[2 * lane + 1]), 0.f);   // channel 2*lane+1
    float t = z0 * W2[2 * lane] + z1 * W2[2 * lane + 1];
#pragma unroll
    for (int off = 16; off; off >>= 1)
        t += __shfl_xor_sync(0xffffffffu, t, off);
    if (lane == 0) g_t[n] = t * d;
}

// ---------------------------------------------------------------- layer-2 gather + padded output
__global__ void k_l2(float* __restrict__ out, const float* __restrict__ b2) {
    int n = (blockIdx.x * 256 + threadIdx.x) >> 5;
    int lane = threadIdx.x & 31;
    if (n >= N_NODES) return;

    int beg = g_off[n];
    int end = beg + g_cnt[n];
    float sum = lane ? 0.f : g_t[n];                // self-loop on lane 0
    for (int j = beg + lane; j < end; j += 32)
        sum += g_t[g_csr[j]];
#pragma unroll
    for (int off = 16; off; off >>= 1)
        sum += __shfl_xor_sync(0xffffffffu, sum, off);

    float y = g_dis[n] * sum + b2[0];
    float4 v = make_float4(0.f, 0.f, 0.f, 0.f);
    if (lane == 0) v.x = y;
    reinterpret_cast<float4*>(out)[(size_t)n * 32 + lane] = v;   // 128 floats/row
}

// ----------------------------------------------------------------
// Fork: gemm (x,W1 only) runs on a side stream concurrently with the edge chain.
// Stream/event created + destroyed within each call: deterministic, no device
// allocation, standard capturable fork/join (event record + StreamWaitEvent).
extern "C" void kernel_launch(void* const* d_in, const int* in_sizes, int n_in,
                              void* d_out, int out_size) {
    const float* x   = (const float*)d_in[0];
    const int*   ei  = (const int*)d_in[1];    // int32 [2, E]
    const float* W1  = (const float*)d_in[2];
    const float* b1  = (const float*)d_in[3];
    const float* W2  = (const float*)d_in[4];
    const float* b2  = (const float*)d_in[5];
    float*       out = (float*)d_out;

    cudaStream_t s2;
    cudaStreamCreateWithFlags(&s2, cudaStreamNonBlocking);
    cudaEvent_t e0, e1;
    cudaEventCreateWithFlags(&e0, cudaEventDisableTiming);
    cudaEventCreateWithFlags(&e1, cudaEventDisableTiming);

    // fork: side stream joins the (possibly capturing) default stream
    cudaEventRecord(e0, 0);
    cudaStreamWaitEvent(s2, e0, 0);
    k_gemm<<<(N_NODES + 255) / 256, 256, 0, s2>>>(x, W1);
    cudaEventRecord(e1, s2);

    // main chain (concurrent with gemm)
    k_cnt_init<<<NB, 256>>>();
    k_deg     <<<(N_EDGES + 255) / 256, 256>>>(ei);
    k_dis     <<<NB, 256>>>();
    k_scan1   <<<NB, 256>>>();
    k_scan2   <<<1, 512>>>();
    k_scan3   <<<NB, 256>>>();
    k_fill    <<<(N_EDGES + 255) / 256, 256>>>(ei);

    // join, then dependent tail
    cudaStreamWaitEvent(0, e1, 0);
    k_gather1 <<<(N_NODES * 32 + 255) / 256, 256>>>(b1, W2);
    k_l2      <<<(N_NODES * 32 + 255) / 256, 256>>>(out, b2);

    cudaEventDestroy(e0);
    cudaEventDestroy(e1);
    cudaStreamDestroy(s2);
}